// round 11
// baseline (speedup 1.0000x reference)
#include <cuda_runtime.h>

// TSModel 2-layer LSTM (layer0: 1->64; layer1: 64->1 fed c0; out = c1/step).
// B=2048 rows, T=1024 steps.
//
// R10 = R8 + K-quarter weight split. 296 CTAs x 256 threads (2 CTAs/SM,
// 7 rows/CTA = balanced 14 rows/SM).
// Warp (gh = wid>>2, kq = wid&3): gate-half gh (gates [128gh,128gh+128)),
// K-quarter kq ([16kq,16kq+16)). Lane owns 4 gates = 2 f32x2-adjacent pairs:
// (128gh+2l, +1) and (128gh+64+2l, +1), weights in 32 ull regs.
// P1: 4 LDS.128 h-broadcast + 32 FFMA2 per row (4 indep acc chains).
// P2 combines the 4 K-quarter partials + cell update. L1 tail on warp 0 only
// (R9 showed distributing it onto all warps serializes every warp's path).

#define UNITS   64
#define TSTEPS  1024
#define ROWS    7
#define NCTA    296
#define NT      256
#define NROWS_TOTAL 2048

typedef unsigned long long ull;

__device__ __forceinline__ ull ffma2(ull a, ull b, ull c) {
    ull d;
    asm("fma.rn.f32x2 %0, %1, %2, %3;" : "=l"(d) : "l"(a), "l"(b), "l"(c));
    return d;
}
__device__ __forceinline__ ull pack2(float x, float y) {
    ull d;
    asm("mov.b64 %0, {%1, %2};" : "=l"(d) : "f"(x), "f"(y));
    return d;
}
__device__ __forceinline__ float2 unpack2(ull v) {
    float2 f;
    asm("mov.b64 {%0, %1}, %2;" : "=f"(f.x), "=f"(f.y) : "l"(v));
    return f;
}
__device__ __forceinline__ float sigf(float x) {
    return __fdividef(1.0f, 1.0f + __expf(-x));
}
__device__ __forceinline__ float tanhfast(float x) {
    return 2.0f * __fdividef(1.0f, 1.0f + __expf(-2.0f * x)) - 1.0f;
}

__global__ void __launch_bounds__(NT, 2)
lstm_kernel(const float* __restrict__ input,
            const float* __restrict__ W_ih0, const float* __restrict__ W_hh0,
            const float* __restrict__ b_ih0, const float* __restrict__ b_hh0,
            const float* __restrict__ W_ih1, const float* __restrict__ W_hh1,
            const float* __restrict__ b_ih1, const float* __restrict__ b_hh1,
            float* __restrict__ out)
{
    __shared__ __align__(16) float gbuf[ROWS][4][256];  // K-quarter partials
    __shared__ __align__(16) float hbuf[ROWS][UNITS];   // h0 state
    __shared__ __align__(16) float cbuf[ROWS][68];      // c0_new (padded)
    __shared__ __align__(16) float xtile[ROWS][64];     // staged input
    __shared__ __align__(16) float W1s[4][68];          // W_ih1

    const int row0 = blockIdx.x * ROWS;
    if (row0 >= NROWS_TOTAL) return;    // fully-OOB CTAs exit

    const int tid  = threadIdx.x;
    const int wid  = tid >> 5;
    const int lane = tid & 31;
    const int gh   = wid >> 2;          // gate half (types 2gh, 2gh+1)
    const int kq   = wid & 3;           // K-quarter

    // ---- one-time init ----
    const int g0 = 128 * gh + 2 * lane;       // pair A: gates g0, g0+1
    const int g1 = g0 + 64;                   // pair C: gates g1, g1+1
    ull wA[8], wB[8], wC[8], wD[8];           // K-slice [16kq,16kq+16) pairs
    {
        const ulonglong2* pa = (const ulonglong2*)(W_hh0 + (g0    ) * UNITS + 16 * kq);
        const ulonglong2* pb = (const ulonglong2*)(W_hh0 + (g0 + 1) * UNITS + 16 * kq);
        const ulonglong2* pc = (const ulonglong2*)(W_hh0 + (g1    ) * UNITS + 16 * kq);
        const ulonglong2* pd = (const ulonglong2*)(W_hh0 + (g1 + 1) * UNITS + 16 * kq);
#pragma unroll
        for (int m = 0; m < 4; m++) {
            ulonglong2 va = pa[m], vb = pb[m], vc = pc[m], vd = pd[m];
            wA[2 * m] = va.x; wA[2 * m + 1] = va.y;
            wB[2 * m] = vb.x; wB[2 * m + 1] = vb.y;
            wC[2 * m] = vc.x; wC[2 * m + 1] = vc.y;
            wD[2 * m] = vd.x; wD[2 * m + 1] = vd.y;
        }
    }
    // x/bias injected only by the kq==0 warps (quarters summed in P2)
    const float wihA = (kq == 0) ? W_ih0[g0]     : 0.0f;
    const float wihB = (kq == 0) ? W_ih0[g0 + 1] : 0.0f;
    const float wihC = (kq == 0) ? W_ih0[g1]     : 0.0f;
    const float wihD = (kq == 0) ? W_ih0[g1 + 1] : 0.0f;
    const float bsA  = (kq == 0) ? (b_ih0[g0]     + b_hh0[g0])     : 0.0f;
    const float bsB  = (kq == 0) ? (b_ih0[g0 + 1] + b_hh0[g0 + 1]) : 0.0f;
    const float bsC  = (kq == 0) ? (b_ih0[g1]     + b_hh0[g1])     : 0.0f;
    const float bsD  = (kq == 0) ? (b_ih0[g1 + 1] + b_hh0[g1 + 1]) : 0.0f;

    float wh1a[4], b1a[4];
#pragma unroll
    for (int k = 0; k < 4; k++) { wh1a[k] = W_hh1[k]; b1a[k] = b_ih1[k] + b_hh1[k]; }
    if (tid < 4 * UNITS) W1s[tid >> 6][tid & 63] = W_ih1[tid];
    {
        float* hb = &hbuf[0][0];
        for (int i = tid; i < ROWS * UNITS; i += NT) hb[i] = 0.0f;
    }

    // P2 identity: unit u2, rows {rs, rs+4} (second row only for rs<3)
    const int u2 = tid & 63;
    const int rs = tid >> 6;            // 0..3
    float c0s[2] = {0.f, 0.f};

    // layer-1 identity (warp 0): row r1 (0..7, clamp), gate q1
    const int r1 = tid >> 2, q1 = tid & 3;
    const int r1c = (r1 < ROWS) ? r1 : (ROWS - 1);
    float h1s = 0.f, c1s = 0.f;

    __syncthreads();

    for (int t = 0; t < TSTEPS; t++) {
        const int tm = t & 63;
        if (tm == 0) {
            // stage 64 timesteps for the CTA's rows (coalesced; clamp OOB)
#pragma unroll
            for (int i = 0; i < 2; i++) {
                int lin = tid + NT * i;
                if (lin < ROWS * 64) {
                    int rr = lin >> 6, cc = lin & 63;
                    int grow = row0 + rr;
                    if (grow > NROWS_TOTAL - 1) grow = NROWS_TOTAL - 1;
                    xtile[rr][cc] = input[grow * TSTEPS + t + cc];
                }
            }
            __syncthreads();
        }

        // ---- P1: 4 gates x 7 rows over this K-quarter; 4 LDS.128 per row ----
#pragma unroll
        for (int r = 0; r < ROWS; r++) {
            const ulonglong2* hv = (const ulonglong2*)(hbuf[r] + 16 * kq);
            float xv = xtile[r][tm];
            ull accA = pack2(fmaf(xv, wihA, bsA), 0.0f);
            ull accB = pack2(fmaf(xv, wihB, bsB), 0.0f);
            ull accC = pack2(fmaf(xv, wihC, bsC), 0.0f);
            ull accD = pack2(fmaf(xv, wihD, bsD), 0.0f);
#pragma unroll
            for (int m = 0; m < 4; m++) {        // 4 x 16B = this K-quarter
                ulonglong2 h2 = hv[m];
                accA = ffma2(h2.x, wA[2 * m], accA);
                accB = ffma2(h2.x, wB[2 * m], accB);
                accC = ffma2(h2.x, wC[2 * m], accC);
                accD = ffma2(h2.x, wD[2 * m], accD);
                accA = ffma2(h2.y, wA[2 * m + 1], accA);
                accB = ffma2(h2.y, wB[2 * m + 1], accB);
                accC = ffma2(h2.y, wC[2 * m + 1], accC);
                accD = ffma2(h2.y, wD[2 * m + 1], accD);
            }
            float2 fa = unpack2(accA), fb = unpack2(accB);
            float2 fc = unpack2(accC), fd = unpack2(accD);
            *(ull*)&gbuf[r][kq][g0] = pack2(fa.x + fa.y, fb.x + fb.y);
            *(ull*)&gbuf[r][kq][g1] = pack2(fc.x + fc.y, fd.x + fd.y);
        }
        __syncthreads();   // S1: partials ready

        // ---- P2: sum 4 K-quarters + layer-0 cell update ----
#pragma unroll
        for (int j = 0; j < 2; j++) {
            const int r = rs + 4 * j;
            if (j == 1 && rs >= ROWS - 4) break;   // rows 4..6 only
            float si = (gbuf[r][0][u2]       + gbuf[r][1][u2])
                     + (gbuf[r][2][u2]       + gbuf[r][3][u2]);
            float sf = (gbuf[r][0][64 + u2]  + gbuf[r][1][64 + u2])
                     + (gbuf[r][2][64 + u2]  + gbuf[r][3][64 + u2]);
            float sg = (gbuf[r][0][128 + u2] + gbuf[r][1][128 + u2])
                     + (gbuf[r][2][128 + u2] + gbuf[r][3][128 + u2]);
            float so = (gbuf[r][0][192 + u2] + gbuf[r][1][192 + u2])
                     + (gbuf[r][2][192 + u2] + gbuf[r][3][192 + u2]);
            float iv = sigf(si), fv = sigf(sf);
            float gv = tanhfast(sg), ov = sigf(so);
            float c  = fmaf(fv, c0s[j], iv * gv);
            c0s[j] = c;
            hbuf[r][u2] = ov * tanhfast(c);
            cbuf[r][u2] = c;   // layer-1 input is the CELL state (ref quirk)
        }
        __syncthreads();   // S2: h, c0_new ready

        // ---- layer 1 (warp 0 only); other warps run ahead to next P1 ----
        if (tid < 32) {
            const ulonglong2* cv = (const ulonglong2*)cbuf[r1c];
            const ulonglong2* wv = (const ulonglong2*)W1s[q1];
            ull pa = 0ULL, pb = 0ULL;
#pragma unroll
            for (int m = 0; m < 16; m++) {       // full 64-element dot
                ulonglong2 c2 = cv[m], w2 = wv[m];
                pa = ffma2(c2.x, w2.x, pa);
                pb = ffma2(c2.y, w2.y, pb);
            }
            float2 fa = unpack2(pa), fb = unpack2(pb);
            float pre = (fa.x + fb.x) + (fa.y + fb.y)
                      + b1a[q1] + wh1a[q1] * h1s;
            float act = (q1 == 2) ? tanhfast(pre) : sigf(pre);

            // gather the 4 gate values within each 4-lane row group
            float a1 = __shfl_xor_sync(0xffffffffu, act, 1);
            float gAv = (q1 & 1) ? a1 : act;    // gate[q & ~1]
            float gBv = (q1 & 1) ? act : a1;    // gate[q | 1]
            float cA = __shfl_xor_sync(0xffffffffu, gAv, 2);
            float cB = __shfl_xor_sync(0xffffffffu, gBv, 2);
            float i1, f1, g1v, o1v;
            if (q1 < 2) { i1 = gAv; f1 = gBv; g1v = cA; o1v = cB; }
            else        { i1 = cA;  f1 = cB;  g1v = gAv; o1v = gBv; }

            float c1n = fmaf(f1, c1s, i1 * g1v);
            c1s = c1n;
            h1s = o1v * tanhfast(c1n);
            if (q1 == 0 && r1 < ROWS && (row0 + r1) < NROWS_TOTAL)
                out[(row0 + r1) * TSTEPS + t] = c1n;
        }
    }
}

extern "C" void kernel_launch(void* const* d_in, const int* in_sizes, int n_in,
                              void* d_out, int out_size) {
    const float* input = (const float*)d_in[0];
    const float* W_ih0 = (const float*)d_in[1];
    const float* W_hh0 = (const float*)d_in[2];
    const float* b_ih0 = (const float*)d_in[3];
    const float* b_hh0 = (const float*)d_in[4];
    const float* W_ih1 = (const float*)d_in[5];
    const float* W_hh1 = (const float*)d_in[6];
    const float* b_ih1 = (const float*)d_in[7];
    const float* b_hh1 = (const float*)d_in[8];
    float* out = (float*)d_out;

    lstm_kernel<<<NCTA, NT>>>(
        input, W_ih0, W_hh0, b_ih0, b_hh0, W_ih1, W_hh1, b_ih1, b_hh1, out);
}

// round 12
// speedup vs baseline: 1.6961x; 1.6961x over previous
#include <cuda_runtime.h>

// TSModel 2-layer LSTM (layer0: 1->64; layer1: 64->1 fed c0; out = c1/step).
// B=2048 rows, T=1024 steps.
//
// R11 = R8 (best: 2073us) + cross-CTA phase stagger.
// R8 recap: 296 CTAs x 256 threads (2 CTAs/SM, 7 rows/CTA). Warp (q, kh) owns
// gate-type q / K-half kh; lane l owns gate pair (64q+2l,+1), weights in 32
// ull regs; h via LDS.128 broadcast. P1 -> gbuf | bar | P2 | bar | tail(w0).
// New: the second co-resident CTA of each SM (blockIdx >= 148 shares an SM
// with blockIdx-148) runs one dummy P2 pass (+bar) before the loop. With
// zeroed gbuf this is a state no-op (c=0.5*0+0.5*tanh(0)=0, h=0) but shifts
// that CTA's cadence so its MUFU/tail windows overlap the partner's FMA-heavy
// P1 instead of phase-locking with it.

#define UNITS   64
#define TSTEPS  1024
#define ROWS    7
#define NCTA    296
#define NT      256
#define NROWS_TOTAL 2048

typedef unsigned long long ull;

__device__ __forceinline__ ull ffma2(ull a, ull b, ull c) {
    ull d;
    asm("fma.rn.f32x2 %0, %1, %2, %3;" : "=l"(d) : "l"(a), "l"(b), "l"(c));
    return d;
}
__device__ __forceinline__ ull pack2(float x, float y) {
    ull d;
    asm("mov.b64 %0, {%1, %2};" : "=l"(d) : "f"(x), "f"(y));
    return d;
}
__device__ __forceinline__ float2 unpack2(ull v) {
    float2 f;
    asm("mov.b64 {%0, %1}, %2;" : "=f"(f.x), "=f"(f.y) : "l"(v));
    return f;
}
__device__ __forceinline__ float sigf(float x) {
    return __fdividef(1.0f, 1.0f + __expf(-x));
}
__device__ __forceinline__ float tanhfast(float x) {
    return 2.0f * __fdividef(1.0f, 1.0f + __expf(-2.0f * x)) - 1.0f;
}

__global__ void __launch_bounds__(NT, 2)
lstm_kernel(const float* __restrict__ input,
            const float* __restrict__ W_ih0, const float* __restrict__ W_hh0,
            const float* __restrict__ b_ih0, const float* __restrict__ b_hh0,
            const float* __restrict__ W_ih1, const float* __restrict__ W_hh1,
            const float* __restrict__ b_ih1, const float* __restrict__ b_hh1,
            float* __restrict__ out)
{
    __shared__ __align__(16) float gbuf[ROWS][2][4][UNITS]; // K-half partials
    __shared__ __align__(16) float hbuf[ROWS][UNITS];       // h0 state
    __shared__ __align__(16) float cbuf[ROWS][68];          // c0_new (padded)
    __shared__ __align__(16) float xtile[ROWS][64];         // staged input
    __shared__ __align__(16) float W1s[4][68];              // W_ih1

    const int row0 = blockIdx.x * ROWS;
    if (row0 >= NROWS_TOTAL) return;    // fully-OOB CTAs exit

    const int tid  = threadIdx.x;
    const int wid  = tid >> 5;
    const int lane = tid & 31;
    const int q    = wid >> 1;          // gate type (i,f,g,o)
    const int kh   = wid & 1;           // K-half

    // ---- one-time init ----
    const int gA = 64 * q + 2 * lane;   // lane's f32x2-adjacent gate pair
    const int gB = gA + 1;
    ull wregA[16], wregB[16];           // weights for K-slice [32kh,32kh+32)
    {
        const ulonglong2* wa = (const ulonglong2*)(W_hh0 + gA * UNITS + 32 * kh);
        const ulonglong2* wb = (const ulonglong2*)(W_hh0 + gB * UNITS + 32 * kh);
#pragma unroll
        for (int m = 0; m < 8; m++) {
            ulonglong2 va = wa[m], vb = wb[m];
            wregA[2 * m] = va.x; wregA[2 * m + 1] = va.y;
            wregB[2 * m] = vb.x; wregB[2 * m + 1] = vb.y;
        }
    }
    // x/bias injected only by the kh==0 warp (halves summed in P2)
    const float wihA = (kh == 0) ? W_ih0[gA] : 0.0f;
    const float wihB = (kh == 0) ? W_ih0[gB] : 0.0f;
    const float bsA  = (kh == 0) ? (b_ih0[gA] + b_hh0[gA]) : 0.0f;
    const float bsB  = (kh == 0) ? (b_ih0[gB] + b_hh0[gB]) : 0.0f;

    float wh1a[4], b1a[4];
#pragma unroll
    for (int k = 0; k < 4; k++) { wh1a[k] = W_hh1[k]; b1a[k] = b_ih1[k] + b_hh1[k]; }
    if (tid < 4 * UNITS) W1s[tid >> 6][tid & 63] = W_ih1[tid];
    {
        float* hb = &hbuf[0][0];
        for (int i = tid; i < ROWS * UNITS; i += NT) hb[i] = 0.0f;
        float* gb = &gbuf[0][0][0][0];
        for (int i = tid; i < ROWS * 2 * 4 * UNITS; i += NT) gb[i] = 0.0f;
    }

    // P2 identity: unit u2, rows {rs, rs+4} (second row only for rs<3)
    const int u2 = tid & 63;
    const int rs = tid >> 6;            // 0..3
    float c0s[2] = {0.f, 0.f};

    // layer-1 identity (warp 0): row r1 (0..7, clamp), gate q1
    const int r1 = tid >> 2, q1 = tid & 3;
    const int r1c = (r1 < ROWS) ? r1 : (ROWS - 1);
    float h1s = 0.f, c1s = 0.f;

    __syncthreads();

    // ---- phase stagger: second co-resident CTA (bid and bid-148 share an
    // SM under the classic bid->smid LUT) runs one dummy P2 (+bar). With
    // gbuf zeroed this leaves all state at 0 but offsets the barrier cadence.
    if (blockIdx.x >= 148) {
#pragma unroll
        for (int j = 0; j < 2; j++) {
            const int r = rs + 4 * j;
            if (j == 1 && rs >= ROWS - 4) break;
            float iv = sigf(gbuf[r][0][0][u2] + gbuf[r][1][0][u2]);
            float fv = sigf(gbuf[r][0][1][u2] + gbuf[r][1][1][u2]);
            float gv = tanhfast(gbuf[r][0][2][u2] + gbuf[r][1][2][u2]);
            float ov = sigf(gbuf[r][0][3][u2] + gbuf[r][1][3][u2]);
            float c  = fmaf(fv, c0s[j], iv * gv);
            c0s[j] = c;
            hbuf[r][u2] = ov * tanhfast(c);
            cbuf[r][u2] = c;
        }
        __syncthreads();
    }

    for (int t = 0; t < TSTEPS; t++) {
        const int tm = t & 63;
        if (tm == 0) {
            // stage 64 timesteps for the CTA's rows (coalesced; clamp OOB)
#pragma unroll
            for (int i = 0; i < 2; i++) {
                int lin = tid + NT * i;
                if (lin < ROWS * 64) {
                    int rr = lin >> 6, cc = lin & 63;
                    int grow = row0 + rr;
                    if (grow > NROWS_TOTAL - 1) grow = NROWS_TOTAL - 1;
                    xtile[rr][cc] = input[grow * TSTEPS + t + cc];
                }
            }
            __syncthreads();
        }

        // ---- P1: 2 gates x 7 rows over this K-half; 8 LDS.128 per row ----
#pragma unroll
        for (int r = 0; r < ROWS; r++) {
            const ulonglong2* hv = (const ulonglong2*)(hbuf[r] + 32 * kh);
            float xv = xtile[r][tm];
            ull accA = pack2(fmaf(xv, wihA, bsA), 0.0f);
            ull accB = pack2(fmaf(xv, wihB, bsB), 0.0f);
#pragma unroll
            for (int m = 0; m < 8; m++) {        // 8 x 16B = this K-half
                ulonglong2 h2 = hv[m];
                accA = ffma2(h2.x, wregA[2 * m],     accA);
                accB = ffma2(h2.x, wregB[2 * m],     accB);
                accA = ffma2(h2.y, wregA[2 * m + 1], accA);
                accB = ffma2(h2.y, wregB[2 * m + 1], accB);
            }
            float2 fa = unpack2(accA), fb = unpack2(accB);
            *(ull*)&gbuf[r][kh][q][2 * lane] = pack2(fa.x + fa.y, fb.x + fb.y);
        }
        __syncthreads();   // S1: partials ready

        // ---- P2: combine K-halves + layer-0 cell update ----
#pragma unroll
        for (int j = 0; j < 2; j++) {
            const int r = rs + 4 * j;
            if (j == 1 && rs >= ROWS - 4) break;   // rows 4..6 only
            float iv = sigf(gbuf[r][0][0][u2] + gbuf[r][1][0][u2]);
            float fv = sigf(gbuf[r][0][1][u2] + gbuf[r][1][1][u2]);
            float gv = tanhfast(gbuf[r][0][2][u2] + gbuf[r][1][2][u2]);
            float ov = sigf(gbuf[r][0][3][u2] + gbuf[r][1][3][u2]);
            float c  = fmaf(fv, c0s[j], iv * gv);
            c0s[j] = c;
            hbuf[r][u2] = ov * tanhfast(c);
            cbuf[r][u2] = c;   // layer-1 input is the CELL state (ref quirk)
        }
        __syncthreads();   // S2: h, c0_new ready

        // ---- layer 1 (warp 0 only); other warps run ahead to next P1 ----
        if (tid < 32) {
            const ulonglong2* cv = (const ulonglong2*)cbuf[r1c];
            const ulonglong2* wv = (const ulonglong2*)W1s[q1];
            ull pa = 0ULL, pb = 0ULL;
#pragma unroll
            for (int m = 0; m < 16; m++) {       // full 64-element dot
                ulonglong2 c2 = cv[m], w2 = wv[m];
                pa = ffma2(c2.x, w2.x, pa);
                pb = ffma2(c2.y, w2.y, pb);
            }
            float2 fa = unpack2(pa), fb = unpack2(pb);
            float pre = (fa.x + fb.x) + (fa.y + fb.y)
                      + b1a[q1] + wh1a[q1] * h1s;
            float act = (q1 == 2) ? tanhfast(pre) : sigf(pre);

            // gather the 4 gate values within each 4-lane row group
            float a1 = __shfl_xor_sync(0xffffffffu, act, 1);
            float gAv = (q1 & 1) ? a1 : act;    // gate[q & ~1]
            float gBv = (q1 & 1) ? act : a1;    // gate[q | 1]
            float cA = __shfl_xor_sync(0xffffffffu, gAv, 2);
            float cB = __shfl_xor_sync(0xffffffffu, gBv, 2);
            float i1, f1, g1v, o1v;
            if (q1 < 2) { i1 = gAv; f1 = gBv; g1v = cA; o1v = cB; }
            else        { i1 = cA;  f1 = cB;  g1v = gAv; o1v = gBv; }

            float c1n = fmaf(f1, c1s, i1 * g1v);
            c1s = c1n;
            h1s = o1v * tanhfast(c1n);
            if (q1 == 0 && r1 < ROWS && (row0 + r1) < NROWS_TOTAL)
                out[(row0 + r1) * TSTEPS + t] = c1n;
        }
    }
}

extern "C" void kernel_launch(void* const* d_in, const int* in_sizes, int n_in,
                              void* d_out, int out_size) {
    const float* input = (const float*)d_in[0];
    const float* W_ih0 = (const float*)d_in[1];
    const float* W_hh0 = (const float*)d_in[2];
    const float* b_ih0 = (const float*)d_in[3];
    const float* b_hh0 = (const float*)d_in[4];
    const float* W_ih1 = (const float*)d_in[5];
    const float* W_hh1 = (const float*)d_in[6];
    const float* b_ih1 = (const float*)d_in[7];
    const float* b_hh1 = (const float*)d_in[8];
    float* out = (float*)d_out;

    lstm_kernel<<<NCTA, NT>>>(
        input, W_ih0, W_hh0, b_ih0, b_hh0, W_ih1, W_hh1, b_ih1, b_hh1, out);
}